// round 9
// baseline (speedup 1.0000x reference)
#include <cuda_runtime.h>
#include <math.h>

// Problem constants
#define SS 64
#define BB 32
#define DM 586
#define DE 583
#define NL 4
#define K1 17
#define CO1 16
#define P1LEN 114
#define KP 21       // combined conv1+pool kernel length
#define CO2 8
#define P2LEN 38
#define CO3 32
#define T3 36
#define NV 128
#define XP 312      // smem x row stride in conv blocks (>= 306 span)
#define NCG 4       // ci groups
#define CIG 8       // ci per group

// Scratch (no allocations allowed)
__device__ float g_rpart[SS*BB*2];                  // per row: {sum, sumsq}
__device__ float g_wsum1[CO1];
__device__ float g_c1part[NCG*SS*CO1*P1LEN];        // raw conv partials per ci-group

// ---------------------------------------------------------------------------
// Kernel U (single launch, 3 independent block families — no intra-launch deps):
//  blocks [0,512):   conv1+avgpool1 partials over 8 ci, gathered DIRECTLY from
//                    emb/pos; combined weights built in-block from w1.
//                    cb = bx: s = cb>>3, pair = (cb>>2)&1, g = cb&3.
//  blocks [512,1024): per-row embedding stats (sum, sumsq) -> g_rpart.
//  blocks [1024,1040): wsum1[co] = sum of raw w1[co].
// ---------------------------------------------------------------------------
__global__ void __launch_bounds__(256)
kU(const int* __restrict__ tokens, const float* __restrict__ emb,
   const float* __restrict__ pos, const float* __restrict__ w1) {
    int bx   = blockIdx.x;
    int tid  = threadIdx.x;
    int wid  = tid >> 5;
    int lane = tid & 31;
    const float scale = sqrtf(586.0f);

    if (bx < 512) {
        // ================= conv partial block =================
        int s    = bx >> 3;
        int pair = (bx >> 2) & 1;
        int g    = bx & 3;
        int p0   = pair ? 58 : 0;
        int CHA  = pair ? 28 : 29;          // both halves of the pair equal
        int offB = CHA * 5;                  // 140 or 145
        int span = (2*CHA - 1)*5 + KP;       // 296 or 306
        int d0   = p0 * 5;

        __shared__ float xs[CIG*XP];                    // 2496
        __shared__ float wraw[CO1*CIG*K1];              // 2176
        __shared__ __align__(16) float ws[CIG*KP*16];   // 2688

        // Gather x slice straight from emb/pos
        #pragma unroll 4
        for (int idx = tid; idx < CIG*XP; idx += 256) {
            int ci = idx / XP;
            int dd = idx - ci*XP;
            float v = 0.f;
            if (dd < span) {
                int d = d0 + dd;
                int rrow = s*BB + g*CIG + ci;
                if (d < DE) {
                    int tok = tokens[rrow];
                    v = emb[(size_t)tok*DE + d] * scale;
                } else {
                    v = pos[rrow*3 + (d - DE)];
                }
            }
            xs[idx] = v;
        }
        // Load raw weight slice: wraw[co*136 + ci*17 + k] = w1[co*544 + g*136 + ...]
        for (int i = tid; i < CO1*CIG*K1; i += 256) {
            int co = i / (CIG*K1);
            int rr = i - co*(CIG*K1);
            wraw[i] = w1[co*(BB*K1) + g*(CIG*K1) + rr];
        }
        __syncthreads();
        // Build combined conv+pool weights for this ci group
        for (int e = tid; e < CIG*KP*16; e += 256) {
            int co = e & 15;
            int t  = e >> 4;
            int m  = t % KP;
            int ci = t / KP;
            int jlo = m - (K1-1); if (jlo < 0) jlo = 0;
            int jhi = m;          if (jhi > 4) jhi = 4;
            float acc = 0.f;
            for (int j = jlo; j <= jhi; j++)
                acc += wraw[co*(CIG*K1) + ci*K1 + (m - j)];
            ws[e] = acc * 0.2f;
        }
        __syncthreads();

        // Two 128-thread halves, one p-chunk each; tile 2co x 2p per thread.
        int half = tid >> 7;
        int t    = tid & 127;
        int pt   = t >> 3;    // p pair base within chunk
        int cop  = t & 7;     // co pair
        int pl0  = pt * 2;
        int co0  = cop * 2;
        float acc00 = 0.f, acc01 = 0.f, acc10 = 0.f, acc11 = 0.f;
        const float* xbase = xs + half*offB + 5*pl0;
        #pragma unroll 2
        for (int ci = 0; ci < CIG; ci++) {
            const float* xr = xbase + ci*XP;
            float xw[26];
            #pragma unroll
            for (int i = 0; i < 26; i++) xw[i] = xr[i];
            const float* wp = ws + ci*(KP*16) + co0;
            #pragma unroll
            for (int m = 0; m < KP; m++) {
                float2 w = *(const float2*)(wp + m*16);
                float x0v = xw[m];
                float x1v = xw[m+5];
                acc00 += w.x * x0v;
                acc01 += w.y * x0v;
                acc10 += w.x * x1v;
                acc11 += w.y * x1v;
            }
        }
        float* dst = g_c1part + ((g*SS + s)*CO1)*P1LEN;
        int pbase = p0 + half*CHA;
        if (pl0 < CHA) {
            int p = pbase + pl0;
            dst[(co0  )*P1LEN + p] = acc00;
            dst[(co0+1)*P1LEN + p] = acc01;
        }
        if (pl0 + 1 < CHA) {
            int p = pbase + pl0 + 1;
            dst[(co0  )*P1LEN + p] = acc10;
            dst[(co0+1)*P1LEN + p] = acc11;
        }
    } else if (bx < 1024) {
        // ================= stats block: 4 rows, 2 warps/row =================
        int r0   = (bx - 512) * 4;
        int r    = r0 + (wid >> 1);
        int part = wid & 1;
        int tok  = tokens[r];
        const float* row = emb + (size_t)tok * DE;
        float sum = 0.f, sq = 0.f;
        int dbase = lane + 32*part;
        #pragma unroll
        for (int k = 0; k < 10; k++) {
            int d = dbase + 64*k;
            if (d < DE) {
                float v = row[d] * scale;
                sum += v; sq += v*v;
            }
        }
        if (part == 0 && lane < 3) {
            float v = pos[r*3 + lane];
            sum += v; sq += v*v;
        }
        #pragma unroll
        for (int off = 16; off >= 1; off >>= 1) {
            sum += __shfl_down_sync(0xffffffffu, sum, off);
            sq  += __shfl_down_sync(0xffffffffu, sq,  off);
        }
        __shared__ float shs[16];
        if (lane == 0) { shs[wid] = sum; shs[8 + wid] = sq; }
        __syncthreads();
        if (tid < 4) {
            g_rpart[(r0 + tid)*2 + 0] = shs[2*tid]     + shs[2*tid + 1];
            g_rpart[(r0 + tid)*2 + 1] = shs[8 + 2*tid] + shs[8 + 2*tid + 1];
        }
    } else {
        // ================= wsum block: one co =================
        int co = bx - 1024;
        const float* wrow = w1 + co*BB*K1;   // 544 floats
        float p = 0.f;
        for (int i = tid; i < BB*K1; i += 256) p += wrow[i];
        #pragma unroll
        for (int off = 16; off >= 1; off >>= 1)
            p += __shfl_down_sync(0xffffffffu, p, off);
        __shared__ float shw[8];
        if (lane == 0) shw[wid] = p;
        __syncthreads();
        if (tid == 0) {
            float q = 0.f;
            #pragma unroll
            for (int i = 0; i < 8; i++) q += shw[i];
            g_wsum1[co] = q;
        }
    }
}

// ---------------------------------------------------------------------------
// Kernel D: fold BN affine from per-row stats, assemble o1 from the 4 conv
// partials, then avgpool2 -> conv2(1x1) -> conv3 (16 ch per block) -> proj ->
// argmax. grid = 128 (64 s x 2 channel halves), block = 256.
// ---------------------------------------------------------------------------
__global__ void __launch_bounds__(256)
kD(const float* __restrict__ gamma, const float* __restrict__ beta,
   const float* __restrict__ b1,
   const float* __restrict__ w2, const float* __restrict__ b2,
   const float* __restrict__ w3, const float* __restrict__ b3,
   const float* __restrict__ wl, const float* __restrict__ bl,
   float* __restrict__ out) {
    int s   = blockIdx.x >> 1;
    int ch  = blockIdx.x & 1;
    int tid = threadIdx.x;
    int wid = tid >> 5;
    int lane = tid & 31;
    __shared__ float o1[CO1*P1LEN];                  // 1824
    __shared__ __align__(16) float wls[NV*T3];       // 4608
    __shared__ float bls[NV];
    __shared__ float o2[CO2*P2LEN];                  // 304
    __shared__ float o3[16*T3];                      // 576
    __shared__ float sAC[2];

    // Warp 0: reduce per-row stats -> BN affine (A, Cf)
    if (wid == 0) {
        float su = g_rpart[(s*BB + lane)*2 + 0];
        float sq = g_rpart[(s*BB + lane)*2 + 1];
        #pragma unroll
        for (int off = 16; off >= 1; off >>= 1) {
            su += __shfl_down_sync(0xffffffffu, su, off);
            sq += __shfl_down_sync(0xffffffffu, sq, off);
        }
        if (lane == 0) {
            float invN = 1.f / (float)(BB*DM);
            float m = su * invN;
            float v = sq * invN - m*m;   // biased var, matches reference
            float A = 1.f, Cf = 0.f;
            #pragma unroll
            for (int l = 0; l < NL; l++) {
                float gg = gamma[l*SS + s];
                float bb = beta[l*SS + s];
                float inv = rsqrtf(v + 1e-5f);
                float a = gg * inv;
                float c = bb - a * m;
                A = a * A;
                Cf = a * Cf + c;
                m = bb;
                v = a * a * v;
            }
            sAC[0] = A; sAC[1] = Cf;
        }
    }
    for (int i = tid; i < NV*T3; i += 256) wls[i] = wl[i];
    if (tid < NV) bls[tid] = bl[tid];
    __syncthreads();

    float A = sAC[0], Cf = sAC[1];
    // o1 assembly: affine(sum of 4 partials) + Cf*wsum + b1
    const float* pp = g_c1part + (s*CO1)*P1LEN;
    for (int i = tid; i < CO1*P1LEN; i += 256) {
        int co = i / P1LEN;
        float acc = ((pp[i] + pp[SS*CO1*P1LEN + i]) + pp[2*SS*CO1*P1LEN + i])
                    + pp[3*SS*CO1*P1LEN + i];
        o1[i] = A*acc + Cf*g_wsum1[co] + b1[co];
    }
    __syncthreads();

    // avgpool(3) then conv2 1x1 (commutes with reference conv2->pool)
    for (int i = tid; i < CO2*P2LEN; i += 256) {
        int c8 = i / P2LEN;
        int q  = i - c8*P2LEN;
        float acc = 0.f;
        #pragma unroll
        for (int ci = 0; ci < CO1; ci++) {
            const float* rr = o1 + ci*P1LEN + 3*q;
            acc += w2[c8*CO1 + ci] * (rr[0] + rr[1] + rr[2]);
        }
        o2[i] = acc * (1.f/3.f) + b2[c8];
    }
    __syncthreads();

    // conv3 for this half's 16 channels: (8,38) -> (16,36)
    for (int i = tid; i < 16*T3; i += 256) {
        int col = i / T3;
        int co  = ch*16 + col;
        int t   = i - col*T3;
        float acc = b3[co];
        #pragma unroll
        for (int c8 = 0; c8 < CO2; c8++) {
            const float* rr = o2 + c8*P2LEN + t;
            const float* w = w3 + (co*CO2 + c8)*3;
            acc += w[0]*rr[0] + w[1]*rr[1] + w[2]*rr[2];
        }
        o3[i] = acc;
    }
    __syncthreads();

    // projection to 128 vocab + argmax (first-max semantics like jnp.argmax)
    int c  = tid >> 4;   // local channel 0..15
    int vl = tid & 15;   // vocab lane
    float orow[T3];
    #pragma unroll
    for (int k = 0; k < T3; k++) orow[k] = o3[c*T3 + k];

    float bestv = -3.4e38f;
    int   besti = 0;
    #pragma unroll
    for (int i = 0; i < 8; i++) {
        int v = vl + 16*i;
        const float4* wr = (const float4*)(wls + v*T3);  // 36 floats = 9 float4
        float d0 = bls[v], d1 = 0.f;
        #pragma unroll
        for (int k4 = 0; k4 < 9; k4 += 2) {
            float4 w4 = wr[k4];
            d0 += orow[4*k4+0]*w4.x + orow[4*k4+1]*w4.y
                + orow[4*k4+2]*w4.z + orow[4*k4+3]*w4.w;
        }
        #pragma unroll
        for (int k4 = 1; k4 < 9; k4 += 2) {
            float4 w4 = wr[k4];
            d1 += orow[4*k4+0]*w4.x + orow[4*k4+1]*w4.y
                + orow[4*k4+2]*w4.z + orow[4*k4+3]*w4.w;
        }
        float d = d0 + d1;
        if (d > bestv) { bestv = d; besti = v; }  // strict > keeps first max in lane
    }
    #pragma unroll
    for (int off = 8; off >= 1; off >>= 1) {
        float ov = __shfl_down_sync(0xffffffffu, bestv, off);
        int   oi = __shfl_down_sync(0xffffffffu, besti, off);
        if (ov > bestv || (ov == bestv && oi < besti)) { bestv = ov; besti = oi; }
    }
    if (vl == 0) out[s*BB + ch*16 + c] = (float)besti;
}

// ---------------------------------------------------------------------------
extern "C" void kernel_launch(void* const* d_in, const int* in_sizes, int n_in,
                              void* d_out, int out_size) {
    const int*   tokens = (const int*)  d_in[0];
    const float* emb    = (const float*)d_in[1];
    const float* pos    = (const float*)d_in[2];
    const float* gamma  = (const float*)d_in[3];
    const float* beta   = (const float*)d_in[4];
    const float* w1     = (const float*)d_in[5];
    const float* b1     = (const float*)d_in[6];
    const float* w2     = (const float*)d_in[7];
    const float* b2     = (const float*)d_in[8];
    const float* w3     = (const float*)d_in[9];
    const float* b3     = (const float*)d_in[10];
    const float* wl     = (const float*)d_in[11];
    const float* bl     = (const float*)d_in[12];
    float* out = (float*)d_out;

    kU<<<1040, 256>>>(tokens, emb, pos, w1);
    kD<<<128, 256>>>(gamma, beta, b1, w2, b2, w3, b3, wl, bl, out);
}

// round 10
// speedup vs baseline: 1.1150x; 1.1150x over previous
#include <cuda_runtime.h>
#include <math.h>

// Problem constants
#define SS 64
#define BB 32
#define DM 586
#define DE 583
#define NL 4
#define K1 17
#define CO1 16
#define CO2 8
#define P2LEN 38
#define CO3 32
#define T3 36
#define NV 128
#define MMW 31      // combined conv1+pool1+conv2+pool2 kernel length
#define XR 592      // smem x row stride in kC (>= 586)
#define NCG 8       // ci groups in kC
#define CIG 4       // ci per group

// Scratch (no allocations allowed)
__device__ float g_x0[SS*BB*DM];
__device__ float g_part[SS*2*2];              // per (s, half): {sum, sumsq}
__device__ float g_W[BB*32*CO2];              // [ci][mm(pad32)][c8] combined weights
__device__ float g_ws2a[CO2];                 // w2 . wsum1
__device__ float g_ws2b[CO2];                 // w2 . b1
__device__ float g_c2part[SS*NCG*CO2*P2LEN];  // raw superconv partials [s][g][c8][q]

// ---------------------------------------------------------------------------
// Kernel S (blocks 0..127): embedding gather (*sqrt(D)) + pos -> g_x0, and
// per-(s,half) partial sums. Block bx: s = bx>>1, rows [16*(bx&1), +16).
// Block 128: build combined superconv weights W, ws2a, ws2b.
// ---------------------------------------------------------------------------
__global__ void __launch_bounds__(1024)
kS(const int* __restrict__ tokens, const float* __restrict__ emb,
   const float* __restrict__ pos, const float* __restrict__ w1,
   const float* __restrict__ w2, const float* __restrict__ b1) {
    int tid  = threadIdx.x;
    int wid  = tid >> 5;
    int lane = tid & 31;

    if (blockIdx.x < 2*SS) {
        int s    = blockIdx.x >> 1;
        int half = blockIdx.x & 1;
        const float scale = sqrtf(586.0f);
        int b    = half*16 + (wid >> 1);   // row within batch
        int part = wid & 1;                // row half covered by this warp
        int tok  = tokens[s*BB + b];
        const float* row = emb + (size_t)tok * DE;
        float* xrow = g_x0 + (size_t)(s*BB + b) * DM;
        float sum = 0.f, sq = 0.f;
        int dbase = lane + 32*part;
        #pragma unroll
        for (int k = 0; k < 10; k++) {
            int d = dbase + 64*k;
            if (d < DE) {
                float v = row[d] * scale;
                xrow[d] = v;
                sum += v; sq += v*v;
            }
        }
        if (part == 0 && lane < 3) {
            float v = pos[(s*BB + b)*3 + lane];
            xrow[DE + lane] = v;
            sum += v; sq += v*v;
        }
        #pragma unroll
        for (int off = 16; off >= 1; off >>= 1) {
            sum += __shfl_down_sync(0xffffffffu, sum, off);
            sq  += __shfl_down_sync(0xffffffffu, sq,  off);
        }
        __shared__ float shs[64];
        if (lane == 0) { shs[wid] = sum; shs[32 + wid] = sq; }
        __syncthreads();
        if (wid == 0) {
            float a = shs[lane];
            float c = shs[32 + lane];
            #pragma unroll
            for (int off = 16; off >= 1; off >>= 1) {
                a += __shfl_down_sync(0xffffffffu, a, off);
                c += __shfl_down_sync(0xffffffffu, c, off);
            }
            if (lane == 0) {
                g_part[(s*2 + half)*2 + 0] = a;
                g_part[(s*2 + half)*2 + 1] = c;
            }
        }
    } else {
        // ================= weight block =================
        __shared__ float sw2[CO2*CO1];                 // 128
        __shared__ float sS2[BB*K1*CO2];               // [ci][k][c8] 4352 floats
        __shared__ float swsum[CO1];
        if (tid < CO2*CO1) sw2[tid] = w2[tid];
        __syncthreads();
        // S2[ci][k][c8] = sum_co1 w2[c8][co1] * w1[co1][ci][k]
        for (int e = tid; e < BB*K1*CO2; e += 1024) {
            int c8 = e & 7;
            int t  = e >> 3;
            int k  = t % K1;
            int ci = t / K1;
            float acc = 0.f;
            #pragma unroll
            for (int co1 = 0; co1 < CO1; co1++)
                acc += sw2[c8*CO1 + co1] * __ldg(&w1[(co1*BB + ci)*K1 + k]);
            sS2[e] = acc;
        }
        // wsum1[co1] = sum of raw w1 row (warps 0..15)
        if (wid < CO1) {
            const float* wrow = w1 + wid*BB*K1;
            float p = 0.f;
            for (int i = lane; i < BB*K1; i += 32) p += wrow[i];
            #pragma unroll
            for (int off = 16; off >= 1; off >>= 1)
                p += __shfl_down_sync(0xffffffffu, p, off);
            if (lane == 0) swsum[wid] = p;
        }
        __syncthreads();
        // W[ci][mm][c8] = (1/15) sum_{d=max(0,mm-16)}^{min(14,mm)} S2[ci][mm-d][c8]
        for (int e = tid; e < BB*MMW*CO2; e += 1024) {
            int c8 = e & 7;
            int t  = e >> 3;
            int mm = t % MMW;
            int ci = t / MMW;
            int dlo = mm - (K1-1); if (dlo < 0) dlo = 0;
            int dhi = mm;          if (dhi > 14) dhi = 14;
            float acc = 0.f;
            for (int d = dlo; d <= dhi; d++)
                acc += sS2[(ci*K1 + (mm - d))*CO2 + c8];
            g_W[(ci*32 + mm)*CO2 + c8] = acc * (1.f/15.f);
        }
        if (tid < CO2) {
            float a = 0.f, bb = 0.f;
            #pragma unroll
            for (int co1 = 0; co1 < CO1; co1++) {
                a  += sw2[tid*CO1 + co1] * swsum[co1];
                bb += sw2[tid*CO1 + co1] * b1[co1];
            }
            g_ws2a[tid] = a;
            g_ws2b[tid] = bb;
        }
    }
}

// ---------------------------------------------------------------------------
// Kernel C: superconv (stride-15, K=31) on g_x0, PARTIAL over 4 ci.
// grid = 512 (64 s x 8 ci-groups), block = 320 (threads 304.. idle in compute).
// Thread = (c8 = t/38, q = t%38): weight LDS broadcast within warp, x LDS
// stride-15 (coprime 32 -> conflict-free). Raw partials only.
// ---------------------------------------------------------------------------
__global__ void __launch_bounds__(320)
kC() {
    int bx = blockIdx.x;
    int s  = bx >> 3;
    int g  = bx & 7;
    int tid = threadIdx.x;

    __shared__ float xs[CIG*XR];            // 2368 floats
    __shared__ float wsl[CIG*32*CO2];       // 1024 floats: [cil][mm][c8]

    for (int idx = tid; idx < CIG*DM; idx += 320) {
        int ci = idx / DM;
        int dd = idx - ci*DM;
        xs[ci*XR + dd] = g_x0[(s*BB + g*CIG + ci)*DM + dd];
    }
    for (int idx = tid; idx < CIG*32*CO2; idx += 320)
        wsl[idx] = g_W[g*(CIG*32*CO2) + idx];
    __syncthreads();

    if (tid < CO2*P2LEN) {
        int c8 = tid / P2LEN;
        int q  = tid - c8*P2LEN;
        float acc0 = 0.f, acc1 = 0.f;
        const float* xb = xs + 15*q;
        #pragma unroll
        for (int ci = 0; ci < CIG; ci++) {
            const float* xr = xb + ci*XR;
            const float* wp = wsl + ci*(32*CO2) + c8;
            #pragma unroll
            for (int mm = 0; mm < MMW; mm += 2) {
                acc0 += wp[mm*CO2] * xr[mm];
                if (mm + 1 < MMW) acc1 += wp[(mm+1)*CO2] * xr[mm+1];
            }
        }
        g_c2part[(s*NCG + g)*(CO2*P2LEN) + tid] = acc0 + acc1;
    }
}

// ---------------------------------------------------------------------------
// Kernel D: fold BN affine, assemble o2 from 8 superconv partials, then
// conv3(K=3, 16 ch per block) -> proj(128x36) -> argmax.
// grid = 128 (64 s x 2 channel halves), block = 256.
// ---------------------------------------------------------------------------
__global__ void __launch_bounds__(256)
kD(const float* __restrict__ gamma, const float* __restrict__ beta,
   const float* __restrict__ b2,
   const float* __restrict__ w3, const float* __restrict__ b3,
   const float* __restrict__ wl, const float* __restrict__ bl,
   float* __restrict__ out) {
    int s   = blockIdx.x >> 1;
    int ch  = blockIdx.x & 1;
    int tid = threadIdx.x;
    __shared__ __align__(16) float wls[NV*T3];       // 4608
    __shared__ float bls[NV];
    __shared__ float o2[CO2*P2LEN];                  // 304
    __shared__ float o3[16*T3];                      // 576

    // BN affine fold (redundant per thread; broadcast loads)
    float A, Cf;
    {
        float invN = 1.f / (float)(BB*DM);
        float ts = g_part[s*4 + 0] + g_part[s*4 + 2];
        float tq = g_part[s*4 + 1] + g_part[s*4 + 3];
        float m = ts * invN;
        float v = tq * invN - m*m;   // biased var, matches reference
        A = 1.f; Cf = 0.f;
        #pragma unroll
        for (int l = 0; l < NL; l++) {
            float gg = gamma[l*SS + s];
            float bb = beta[l*SS + s];
            float inv = rsqrtf(v + 1e-5f);
            float a = gg * inv;
            float c = bb - a * m;
            A = a * A;
            Cf = a * Cf + c;
            m = bb;
            v = a * a * v;
        }
    }

    // o2 assembly: A*(sum of 8 partials) + Cf*ws2a + ws2b + b2
    const float* pp = g_c2part + s*NCG*(CO2*P2LEN);
    for (int i = tid; i < CO2*P2LEN; i += 256) {
        int c8 = i / P2LEN;
        float acc = ((pp[i] + pp[304 + i]) + (pp[2*304 + i] + pp[3*304 + i]))
                  + ((pp[4*304 + i] + pp[5*304 + i]) + (pp[6*304 + i] + pp[7*304 + i]));
        o2[i] = A*acc + Cf*g_ws2a[c8] + g_ws2b[c8] + b2[c8];
    }
    for (int i = tid; i < NV*T3; i += 256) wls[i] = wl[i];
    if (tid < NV) bls[tid] = bl[tid];
    __syncthreads();

    // conv3 for this half's 16 channels: (8,38) -> (16,36)
    for (int i = tid; i < 16*T3; i += 256) {
        int col = i / T3;
        int co  = ch*16 + col;
        int t   = i - col*T3;
        float acc = b3[co];
        #pragma unroll
        for (int c8 = 0; c8 < CO2; c8++) {
            const float* rr = o2 + c8*P2LEN + t;
            const float* w = w3 + (co*CO2 + c8)*3;
            acc += w[0]*rr[0] + w[1]*rr[1] + w[2]*rr[2];
        }
        o3[i] = acc;
    }
    __syncthreads();

    // projection to 128 vocab + argmax (first-max semantics like jnp.argmax)
    int c  = tid >> 4;   // local channel 0..15
    int vl = tid & 15;   // vocab lane
    float orow[T3];
    #pragma unroll
    for (int k = 0; k < T3; k++) orow[k] = o3[c*T3 + k];

    float bestv = -3.4e38f;
    int   besti = 0;
    #pragma unroll
    for (int i = 0; i < 8; i++) {
        int v = vl + 16*i;
        const float4* wr = (const float4*)(wls + v*T3);  // 36 floats = 9 float4
        float d0 = bls[v], d1 = 0.f;
        #pragma unroll
        for (int k4 = 0; k4 < 9; k4 += 2) {
            float4 w4 = wr[k4];
            d0 += orow[4*k4+0]*w4.x + orow[4*k4+1]*w4.y
                + orow[4*k4+2]*w4.z + orow[4*k4+3]*w4.w;
        }
        #pragma unroll
        for (int k4 = 1; k4 < 9; k4 += 2) {
            float4 w4 = wr[k4];
            d1 += orow[4*k4+0]*w4.x + orow[4*k4+1]*w4.y
                + orow[4*k4+2]*w4.z + orow[4*k4+3]*w4.w;
        }
        float d = d0 + d1;
        if (d > bestv) { bestv = d; besti = v; }  // strict > keeps first max in lane
    }
    #pragma unroll
    for (int off = 8; off >= 1; off >>= 1) {
        float ov = __shfl_down_sync(0xffffffffu, bestv, off);
        int   oi = __shfl_down_sync(0xffffffffu, besti, off);
        if (ov > bestv || (ov == bestv && oi < besti)) { bestv = ov; besti = oi; }
    }
    if (vl == 0) out[s*BB + ch*16 + c] = (float)besti;
}

// ---------------------------------------------------------------------------
extern "C" void kernel_launch(void* const* d_in, const int* in_sizes, int n_in,
                              void* d_out, int out_size) {
    const int*   tokens = (const int*)  d_in[0];
    const float* emb    = (const float*)d_in[1];
    const float* pos    = (const float*)d_in[2];
    const float* gamma  = (const float*)d_in[3];
    const float* beta   = (const float*)d_in[4];
    const float* w1     = (const float*)d_in[5];
    const float* b1     = (const float*)d_in[6];
    const float* w2     = (const float*)d_in[7];
    const float* b2     = (const float*)d_in[8];
    const float* w3     = (const float*)d_in[9];
    const float* b3     = (const float*)d_in[10];
    const float* wl     = (const float*)d_in[11];
    const float* bl     = (const float*)d_in[12];
    float* out = (float*)d_out;

    kS<<<2*SS + 1, 1024>>>(tokens, emb, pos, w1, w2, b1);
    kC<<<512, 320>>>();
    kD<<<128, 256>>>(gamma, beta, b2, w3, b3, wl, bl, out);
}

// round 11
// speedup vs baseline: 1.4517x; 1.3019x over previous
#include <cuda_runtime.h>
#include <math.h>

// Problem constants
#define SS 64
#define BB 32
#define DM 586
#define DE 583
#define NL 4
#define K1 17
#define CO1 16
#define CO2 8
#define P2LEN 38
#define CO3 32
#define T3 36
#define NV 128
#define MMW 31      // combined conv1+pool1+conv2+pool2 kernel length
#define XR 592      // smem x row stride in kC (>= 586)
#define NCG 8       // ci groups in kC
#define CIG 4       // ci per group

// Scratch (no allocations allowed)
__device__ float g_x0[SS*BB*DM];
__device__ float g_part[SS*2*2];              // per (s, half): {sum, sumsq}
__device__ float g_W[BB*32*CO2];              // [ci][mm(pad32)][c8] combined weights
__device__ float g_ws2a[CO2];                 // w2 . wsum1
__device__ float g_ws2b[CO2];                 // w2 . b1
__device__ float g_c2part[SS*NCG*CO2*P2LEN];  // raw superconv partials [s][g][c8][q]

// ---------------------------------------------------------------------------
// Kernel S (blocks 0..127): embedding gather (*sqrt(D)) + pos -> g_x0, and
// per-(s,half) partial sums. Block bx: s = bx>>1, rows [16*(bx&1), +16).
// Blocks 128..135: combined superconv weights for c8 = bx-128 (w1 staged
// through smem, coalesced once; all math from smem).
// ---------------------------------------------------------------------------
__global__ void __launch_bounds__(1024)
kS(const int* __restrict__ tokens, const float* __restrict__ emb,
   const float* __restrict__ pos, const float* __restrict__ w1,
   const float* __restrict__ w2, const float* __restrict__ b1) {
    int tid  = threadIdx.x;
    int wid  = tid >> 5;
    int lane = tid & 31;

    if (blockIdx.x < 2*SS) {
        int s    = blockIdx.x >> 1;
        int half = blockIdx.x & 1;
        const float scale = sqrtf(586.0f);
        int b    = half*16 + (wid >> 1);   // row within batch
        int part = wid & 1;                // row half covered by this warp
        int tok  = tokens[s*BB + b];
        const float* row = emb + (size_t)tok * DE;
        float* xrow = g_x0 + (size_t)(s*BB + b) * DM;
        float sum = 0.f, sq = 0.f;
        int dbase = lane + 32*part;
        #pragma unroll
        for (int k = 0; k < 10; k++) {
            int d = dbase + 64*k;
            if (d < DE) {
                float v = row[d] * scale;
                xrow[d] = v;
                sum += v; sq += v*v;
            }
        }
        if (part == 0 && lane < 3) {
            float v = pos[(s*BB + b)*3 + lane];
            xrow[DE + lane] = v;
            sum += v; sq += v*v;
        }
        #pragma unroll
        for (int off = 16; off >= 1; off >>= 1) {
            sum += __shfl_down_sync(0xffffffffu, sum, off);
            sq  += __shfl_down_sync(0xffffffffu, sq,  off);
        }
        __shared__ float shs[64];
        if (lane == 0) { shs[wid] = sum; shs[32 + wid] = sq; }
        __syncthreads();
        if (wid == 0) {
            float a = shs[lane];
            float c = shs[32 + lane];
            #pragma unroll
            for (int off = 16; off >= 1; off >>= 1) {
                a += __shfl_down_sync(0xffffffffu, a, off);
                c += __shfl_down_sync(0xffffffffu, c, off);
            }
            if (lane == 0) {
                g_part[(s*2 + half)*2 + 0] = a;
                g_part[(s*2 + half)*2 + 1] = c;
            }
        }
    } else {
        // ============== weight block for one c8 ==============
        int c8 = blockIdx.x - 2*SS;
        extern __shared__ float dyn[];
        float* sw1 = dyn;                   // CO1*BB*K1 = 8704 floats
        float* sS2 = dyn + CO1*BB*K1;       // BB*K1 = 544 floats
        __shared__ float sw2c[CO1];
        __shared__ float swsum[CO1];

        if (tid < CO1) sw2c[tid] = w2[c8*CO1 + tid];
        for (int i = tid; i < CO1*BB*K1; i += 1024) sw1[i] = w1[i];
        __syncthreads();

        // S2[ci*K1+k] = sum_co1 w2[c8][co1] * w1[co1][ci][k]
        if (tid < BB*K1) {
            float acc = 0.f;
            #pragma unroll
            for (int co1 = 0; co1 < CO1; co1++)
                acc += sw2c[co1] * sw1[co1*(BB*K1) + tid];
            sS2[tid] = acc;
        }
        // wsum1[co1] (warps 0..15, from smem)
        if (wid < CO1) {
            float p = 0.f;
            for (int i = lane; i < BB*K1; i += 32) p += sw1[wid*(BB*K1) + i];
            #pragma unroll
            for (int off = 16; off >= 1; off >>= 1)
                p += __shfl_down_sync(0xffffffffu, p, off);
            if (lane == 0) swsum[wid] = p;
        }
        __syncthreads();

        // W[ci][mm][c8] = (1/15) sum_{d=max(0,mm-16)}^{min(14,mm)} S2[ci][mm-d]
        for (int e = tid; e < BB*MMW; e += 1024) {
            int mm = e % MMW;
            int ci = e / MMW;
            int dlo = mm - (K1-1); if (dlo < 0) dlo = 0;
            int dhi = mm;          if (dhi > 14) dhi = 14;
            float acc = 0.f;
            for (int d = dlo; d <= dhi; d++)
                acc += sS2[ci*K1 + (mm - d)];
            g_W[(ci*32 + mm)*CO2 + c8] = acc * (1.f/15.f);
        }
        if (tid == 0) {
            float a = 0.f, bb = 0.f;
            #pragma unroll
            for (int co1 = 0; co1 < CO1; co1++) {
                a  += sw2c[co1] * swsum[co1];
                bb += sw2c[co1] * b1[co1];
            }
            g_ws2a[c8] = a;
            g_ws2b[c8] = bb;
        }
    }
}

// ---------------------------------------------------------------------------
// Kernel C: superconv (stride-15, K=31) on g_x0, PARTIAL over 4 ci.
// grid = 512 (64 s x 8 ci-groups), block = 320 (threads 304.. idle in compute).
// Thread = (c8 = t/38, q = t%38): weight LDS broadcast within warp, x LDS
// stride-15 (coprime 32 -> conflict-free). Raw partials only.
// ---------------------------------------------------------------------------
__global__ void __launch_bounds__(320)
kC() {
    int bx = blockIdx.x;
    int s  = bx >> 3;
    int g  = bx & 7;
    int tid = threadIdx.x;

    __shared__ float xs[CIG*XR];            // 2368 floats
    __shared__ float wsl[CIG*32*CO2];       // 1024 floats: [cil][mm][c8]

    for (int idx = tid; idx < CIG*DM; idx += 320) {
        int ci = idx / DM;
        int dd = idx - ci*DM;
        xs[ci*XR + dd] = g_x0[(s*BB + g*CIG + ci)*DM + dd];
    }
    for (int idx = tid; idx < CIG*32*CO2; idx += 320)
        wsl[idx] = g_W[g*(CIG*32*CO2) + idx];
    __syncthreads();

    if (tid < CO2*P2LEN) {
        int c8 = tid / P2LEN;
        int q  = tid - c8*P2LEN;
        float acc0 = 0.f, acc1 = 0.f;
        const float* xb = xs + 15*q;
        #pragma unroll
        for (int ci = 0; ci < CIG; ci++) {
            const float* xr = xb + ci*XR;
            const float* wp = wsl + ci*(32*CO2) + c8;
            #pragma unroll
            for (int mm = 0; mm < MMW; mm += 2) {
                acc0 += wp[mm*CO2] * xr[mm];
                if (mm + 1 < MMW) acc1 += wp[(mm+1)*CO2] * xr[mm+1];
            }
        }
        g_c2part[(s*NCG + g)*(CO2*P2LEN) + tid] = acc0 + acc1;
    }
}

// ---------------------------------------------------------------------------
// Kernel D: fold BN affine, assemble o2 from 8 superconv partials, then
// conv3(K=3, 16 ch per block) -> proj(128x36) -> argmax.
// grid = 128 (64 s x 2 channel halves), block = 256.
// ---------------------------------------------------------------------------
__global__ void __launch_bounds__(256)
kD(const float* __restrict__ gamma, const float* __restrict__ beta,
   const float* __restrict__ b2,
   const float* __restrict__ w3, const float* __restrict__ b3,
   const float* __restrict__ wl, const float* __restrict__ bl,
   float* __restrict__ out) {
    int s   = blockIdx.x >> 1;
    int ch  = blockIdx.x & 1;
    int tid = threadIdx.x;
    __shared__ __align__(16) float wls[NV*T3];       // 4608
    __shared__ float bls[NV];
    __shared__ float o2[CO2*P2LEN];                  // 304
    __shared__ float o3[16*T3];                      // 576

    // BN affine fold (redundant per thread; broadcast loads)
    float A, Cf;
    {
        float invN = 1.f / (float)(BB*DM);
        float ts = g_part[s*4 + 0] + g_part[s*4 + 2];
        float tq = g_part[s*4 + 1] + g_part[s*4 + 3];
        float m = ts * invN;
        float v = tq * invN - m*m;   // biased var, matches reference
        A = 1.f; Cf = 0.f;
        #pragma unroll
        for (int l = 0; l < NL; l++) {
            float gg = gamma[l*SS + s];
            float bb = beta[l*SS + s];
            float inv = rsqrtf(v + 1e-5f);
            float a = gg * inv;
            float c = bb - a * m;
            A = a * A;
            Cf = a * Cf + c;
            m = bb;
            v = a * a * v;
        }
    }

    // o2 assembly: A*(sum of 8 partials) + Cf*ws2a + ws2b + b2
    const float* pp = g_c2part + s*NCG*(CO2*P2LEN);
    for (int i = tid; i < CO2*P2LEN; i += 256) {
        int c8 = i / P2LEN;
        float acc = ((pp[i] + pp[304 + i]) + (pp[2*304 + i] + pp[3*304 + i]))
                  + ((pp[4*304 + i] + pp[5*304 + i]) + (pp[6*304 + i] + pp[7*304 + i]));
        o2[i] = A*acc + Cf*g_ws2a[c8] + g_ws2b[c8] + b2[c8];
    }
    for (int i = tid; i < NV*T3; i += 256) wls[i] = wl[i];
    if (tid < NV) bls[tid] = bl[tid];
    __syncthreads();

    // conv3 for this half's 16 channels: (8,38) -> (16,36)
    for (int i = tid; i < 16*T3; i += 256) {
        int col = i / T3;
        int co  = ch*16 + col;
        int t   = i - col*T3;
        float acc = b3[co];
        #pragma unroll
        for (int c8 = 0; c8 < CO2; c8++) {
            const float* rr = o2 + c8*P2LEN + t;
            const float* w = w3 + (co*CO2 + c8)*3;
            acc += w[0]*rr[0] + w[1]*rr[1] + w[2]*rr[2];
        }
        o3[i] = acc;
    }
    __syncthreads();

    // projection to 128 vocab + argmax (first-max semantics like jnp.argmax)
    int c  = tid >> 4;   // local channel 0..15
    int vl = tid & 15;   // vocab lane
    float orow[T3];
    #pragma unroll
    for (int k = 0; k < T3; k++) orow[k] = o3[c*T3 + k];

    float bestv = -3.4e38f;
    int   besti = 0;
    #pragma unroll
    for (int i = 0; i < 8; i++) {
        int v = vl + 16*i;
        const float4* wr = (const float4*)(wls + v*T3);  // 36 floats = 9 float4
        float d0 = bls[v], d1 = 0.f;
        #pragma unroll
        for (int k4 = 0; k4 < 9; k4 += 2) {
            float4 w4 = wr[k4];
            d0 += orow[4*k4+0]*w4.x + orow[4*k4+1]*w4.y
                + orow[4*k4+2]*w4.z + orow[4*k4+3]*w4.w;
        }
        #pragma unroll
        for (int k4 = 1; k4 < 9; k4 += 2) {
            float4 w4 = wr[k4];
            d1 += orow[4*k4+0]*w4.x + orow[4*k4+1]*w4.y
                + orow[4*k4+2]*w4.z + orow[4*k4+3]*w4.w;
        }
        float d = d0 + d1;
        if (d > bestv) { bestv = d; besti = v; }  // strict > keeps first max in lane
    }
    #pragma unroll
    for (int off = 8; off >= 1; off >>= 1) {
        float ov = __shfl_down_sync(0xffffffffu, bestv, off);
        int   oi = __shfl_down_sync(0xffffffffu, besti, off);
        if (ov > bestv || (ov == bestv && oi < besti)) { bestv = ov; besti = oi; }
    }
    if (vl == 0) out[s*BB + ch*16 + c] = (float)besti;
}

// ---------------------------------------------------------------------------
extern "C" void kernel_launch(void* const* d_in, const int* in_sizes, int n_in,
                              void* d_out, int out_size) {
    const int*   tokens = (const int*)  d_in[0];
    const float* emb    = (const float*)d_in[1];
    const float* pos    = (const float*)d_in[2];
    const float* gamma  = (const float*)d_in[3];
    const float* beta   = (const float*)d_in[4];
    const float* w1     = (const float*)d_in[5];
    const float* b1     = (const float*)d_in[6];
    const float* w2     = (const float*)d_in[7];
    const float* b2     = (const float*)d_in[8];
    const float* w3     = (const float*)d_in[9];
    const float* b3     = (const float*)d_in[10];
    const float* wl     = (const float*)d_in[11];
    const float* bl     = (const float*)d_in[12];
    float* out = (float*)d_out;

    size_t shS = (size_t)(CO1*BB*K1 + BB*K1) * sizeof(float);  // 36992 B
    kS<<<2*SS + CO2, 1024, shS>>>(tokens, emb, pos, w1, w2, b1);
    kC<<<512, 320>>>();
    kD<<<128, 256>>>(gamma, beta, b2, w3, b3, wl, bl, out);
}